// round 15
// baseline (speedup 1.0000x reference)
#include <cuda_runtime.h>
#include <math.h>

// Problem constants (fixed by the dataset)
#define N_NODES 80000
#define N_EDGES 64000
#define NB 32
#define NG 2500
#define NA 50
#define HDIM 64
#define EDIM 16
#define HG 128
#define FIN 159   // 64 + 95
#define AF 95
#define KST 3
#define TLY 6

#define E_TILES (N_EDGES / 64)    // 1000 edge tiles of 64 edges
#define R_TILES (N_NODES / 64)    // 1250

typedef unsigned long long ull;

__device__ __forceinline__ ull fma2(ull a, ull b, ull c) {
    ull d; asm("fma.rn.f32x2 %0, %1, %2, %3;" : "=l"(d) : "l"(a), "l"(b), "l"(c)); return d;
}
__device__ __forceinline__ ull pack2(float x, float y) {
    ull d; asm("mov.b64 %0, {%1, %2};" : "=l"(d) : "f"(x), "f"(y)); return d;
}
__device__ __forceinline__ float2 unpack2(ull v) {
    float2 r; asm("mov.b64 {%0, %1}, %2;" : "=f"(r.x), "=f"(r.y) : "l"(v)); return r;
}

// PDL: wait for the programmatic-dependency (previous kernel).
#define GDS() cudaGridDependencySynchronize()

// Scratch (device globals; no runtime allocation allowed)
__device__ float g_h1[N_NODES * HDIM];
__device__ float g_h2[N_NODES * HDIM];
__device__ float g_sc[NB * NG];
__device__ float g_amino[NB * NA * HDIM];
__device__ float g_Z0[KST * NB * NA * HG];
__device__ float g_R[TLY * KST * NB * NA * HG];
__device__ float g_outF[KST * NB * NA * HG];

// ---------------------------------------------------------------------------
// Zero both accumulator buffers (single launch, no upstream dependency).
// ---------------------------------------------------------------------------
__global__ void zero_kernel(float* __restrict__ a, float* __restrict__ b)
{
    const int stride = gridDim.x * blockDim.x;
    const float4 z = make_float4(0.f, 0.f, 0.f, 0.f);
    for (int i = blockIdx.x * blockDim.x + threadIdx.x; i < (N_NODES * HDIM) / 4; i += stride) {
        reinterpret_cast<float4*>(a)[i] = z;
        reinterpret_cast<float4*>(b)[i] = z;
    }
}

// ---------------------------------------------------------------------------
// Fused NNConv, 3-CTA/SM variant: blocks [0, E_TILES) = edge path (64 edges x
// 64 outs, FFMA2, broadcast-B double-buffered in smem, one sync per j, 4x4
// micro-tile -> <=83 regs); blocks [E_TILES, +R_TILES) = root path. atomicAdd.
// ---------------------------------------------------------------------------
template <bool RELU>
__global__ __launch_bounds__(256, 3) void conv_kernel(
    const float* __restrict__ h, const int* __restrict__ src,
    const int* __restrict__ dst, const float* __restrict__ ea,
    const float* __restrict__ we, const float* __restrict__ be,
    const float* __restrict__ root, const float* __restrict__ bias,
    float* __restrict__ agg)
{
    extern __shared__ float sm[];
    const int tid = threadIdx.x;
    GDS();

    if (blockIdx.x < E_TILES) {
        // ------------- edge path -------------
        float* Hs  = sm;             // [64][64]   Hs[i*64+e]
        float* Bs  = sm + 4096;      // 2 x [64][64]
        float* Eas = sm + 12288;     // [17][64]

        const int e0 = blockIdx.x * 64;
        {
            const int e = tid & 63;
            const int ge = e0 + e;
            const int quarter = tid >> 6;   // 0..3
            const int s = src[ge];
            const float4* hp = reinterpret_cast<const float4*>(h + (size_t)s * 64) + quarter * 4;
#pragma unroll
            for (int r = 0; r < 4; ++r) {
                float4 v = hp[r];
                if (RELU) { v.x = fmaxf(v.x, 0.f); v.y = fmaxf(v.y, 0.f); v.z = fmaxf(v.z, 0.f); v.w = fmaxf(v.w, 0.f); }
                const int i = quarter * 16 + r * 4;
                Hs[(i + 0) * 64 + e] = v.x; Hs[(i + 1) * 64 + e] = v.y;
                Hs[(i + 2) * 64 + e] = v.z; Hs[(i + 3) * 64 + e] = v.w;
            }
            const float4 cq = reinterpret_cast<const float4*>(ea + (size_t)ge * 16)[quarter];
            const int jb = quarter * 4;
            Eas[(jb + 0) * 64 + e] = cq.x; Eas[(jb + 1) * 64 + e] = cq.y;
            Eas[(jb + 2) * 64 + e] = cq.z; Eas[(jb + 3) * 64 + e] = cq.w;
            if (tid < 64) Eas[16 * 64 + tid] = 1.0f;
        }

        // prefetch B_0 and store into buffer 0 (no cross-thread hazard)
        float4 breg[4];
        {
            const float4* Bsrc = reinterpret_cast<const float4*>(we);
#pragma unroll
            for (int r = 0; r < 4; ++r) breg[r] = Bsrc[tid + r * 256];
            float4* d = reinterpret_cast<float4*>(Bs);
#pragma unroll
            for (int r = 0; r < 4; ++r) d[tid + r * 256] = breg[r];
        }
        __syncthreads();   // Hs/Eas/B0 visible

        const int eg = (tid >> 4) * 4;    // 16 edge-groups of 4 (2 packed pairs)
        const int og = (tid & 15) * 4;    // 16 out-groups of 4

        ull acc[2][4];
#pragma unroll
        for (int p = 0; p < 2; ++p)
#pragma unroll
            for (int q = 0; q < 4; ++q) acc[p][q] = 0ull;

        for (int j = 0; j < 17; ++j) {
            if (j < 16) {
                const float4* Bsrc = reinterpret_cast<const float4*>(j < 15 ? we + (size_t)(j + 1) * 4096 : be);
#pragma unroll
                for (int r = 0; r < 4; ++r) breg[r] = Bsrc[tid + r * 256];
            }
            const float* Bcur = Bs + (j & 1) * 4096;

            ull t[2][4];
#pragma unroll
            for (int p = 0; p < 2; ++p)
#pragma unroll
                for (int q = 0; q < 4; ++q) t[p][q] = 0ull;

#pragma unroll 8
            for (int i = 0; i < 64; ++i) {
                const ulonglong2 h01 = *reinterpret_cast<const ulonglong2*>(&Hs[i * 64 + eg]);
                const float4 bv = *reinterpret_cast<const float4*>(&Bcur[i * 64 + og]);
                const ull b0 = pack2(bv.x, bv.x), b1 = pack2(bv.y, bv.y);
                const ull b2 = pack2(bv.z, bv.z), b3 = pack2(bv.w, bv.w);
                t[0][0] = fma2(h01.x, b0, t[0][0]); t[0][1] = fma2(h01.x, b1, t[0][1]);
                t[0][2] = fma2(h01.x, b2, t[0][2]); t[0][3] = fma2(h01.x, b3, t[0][3]);
                t[1][0] = fma2(h01.y, b0, t[1][0]); t[1][1] = fma2(h01.y, b1, t[1][1]);
                t[1][2] = fma2(h01.y, b2, t[1][2]); t[1][3] = fma2(h01.y, b3, t[1][3]);
            }
            const ulonglong2 c01 = *reinterpret_cast<const ulonglong2*>(&Eas[j * 64 + eg]);
#pragma unroll
            for (int q = 0; q < 4; ++q) {
                acc[0][q] = fma2(c01.x, t[0][q], acc[0][q]);
                acc[1][q] = fma2(c01.y, t[1][q], acc[1][q]);
            }
            if (j < 16) {
                float4* d = reinterpret_cast<float4*>(Bs + ((j + 1) & 1) * 4096);
#pragma unroll
                for (int r = 0; r < 4; ++r) d[tid + r * 256] = breg[r];
            }
            __syncthreads();
        }

#pragma unroll
        for (int p = 0; p < 2; ++p) {
            const int d0 = dst[e0 + eg + 2 * p];
            const int d1 = dst[e0 + eg + 2 * p + 1];
            float* p0 = agg + (size_t)d0 * 64 + og;
            float* p1 = agg + (size_t)d1 * 64 + og;
#pragma unroll
            for (int q = 0; q < 4; ++q) {
                const float2 v = unpack2(acc[p][q]);
                atomicAdd(p0 + q, v.x);
                atomicAdd(p1 + q, v.y);
            }
        }
    } else {
        // ------------- root path -------------
        float* Hs = sm;           // [64][64]  Hs[i*64+node]
        float* Bs = sm + 4096;    // [64][64]
        const int n0 = (blockIdx.x - E_TILES) * 64;
        {
            const int e = tid & 63;
            const float4* hp = reinterpret_cast<const float4*>(h + (size_t)(n0 + e) * 64);
#pragma unroll
            for (int r = 0; r < 4; ++r) {
                const int i4 = (tid >> 6) + r * 4;
                float4 v = hp[i4];
                if (RELU) { v.x = fmaxf(v.x, 0.f); v.y = fmaxf(v.y, 0.f); v.z = fmaxf(v.z, 0.f); v.w = fmaxf(v.w, 0.f); }
                Hs[(i4 * 4 + 0) * 64 + e] = v.x; Hs[(i4 * 4 + 1) * 64 + e] = v.y;
                Hs[(i4 * 4 + 2) * 64 + e] = v.z; Hs[(i4 * 4 + 3) * 64 + e] = v.w;
            }
        }
        for (int idx = tid; idx < 1024; idx += 256)
            reinterpret_cast<float4*>(Bs)[idx] = reinterpret_cast<const float4*>(root)[idx];
        __syncthreads();

        // 2x4 micro-tile x2 serial row-halves (register cap 83)
        const int ty = (tid >> 4) * 4;    // 16 row groups of 4
        const int tx4 = (tid & 15) * 4;   // 16 col groups of 4
#pragma unroll
        for (int half = 0; half < 2; ++half) {
            const int r0 = ty + half * 2;   // 2 rows per pass
            float acc[2][4];
            const float4 bb = *reinterpret_cast<const float4*>(bias + tx4);
#pragma unroll
            for (int a = 0; a < 2; ++a) { acc[a][0] = bb.x; acc[a][1] = bb.y; acc[a][2] = bb.z; acc[a][3] = bb.w; }
#pragma unroll 8
            for (int i = 0; i < 64; ++i) {
                float hv[2], bv[4];
                hv[0] = Hs[i * 64 + r0];
                hv[1] = Hs[i * 64 + r0 + 1];
                *reinterpret_cast<float4*>(bv) = *reinterpret_cast<const float4*>(&Bs[i * 64 + tx4]);
#pragma unroll
                for (int a = 0; a < 2; ++a)
#pragma unroll
                    for (int q = 0; q < 4; ++q) acc[a][q] = fmaf(hv[a], bv[q], acc[a][q]);
            }
#pragma unroll
            for (int a = 0; a < 2; ++a) {
                float* p = agg + (size_t)(n0 + r0 + a) * 64 + tx4;
#pragma unroll
                for (int q = 0; q < 4; ++q) atomicAdd(p + q, acc[a][q]);
            }
        }
    }
}

// ---------------------------------------------------------------------------
// Readout stage A: per-atom attention scores. Grid = 2500, 32 atoms/block.
// ---------------------------------------------------------------------------
__global__ __launch_bounds__(256) void score_kernel(const float* __restrict__ attw)
{
    const int tid = threadIdx.x;
    const int q = tid & 7;
    const int atom = blockIdx.x * 32 + (tid >> 3);
    GDS();
    const float4 aw0 = *reinterpret_cast<const float4*>(attw + q * 8);
    const float4 aw1 = *reinterpret_cast<const float4*>(attw + q * 8 + 4);
    const float* hr = g_h2 + (size_t)atom * 64 + q * 8;
    const float4 u0 = *reinterpret_cast<const float4*>(hr);
    const float4 u1 = *reinterpret_cast<const float4*>(hr + 4);
    float v = fmaxf(u0.x, 0.f) * aw0.x + fmaxf(u0.y, 0.f) * aw0.y +
              fmaxf(u0.z, 0.f) * aw0.z + fmaxf(u0.w, 0.f) * aw0.w +
              fmaxf(u1.x, 0.f) * aw1.x + fmaxf(u1.y, 0.f) * aw1.y +
              fmaxf(u1.z, 0.f) * aw1.z + fmaxf(u1.w, 0.f) * aw1.w;
    v += __shfl_xor_sync(0xffffffffu, v, 4);
    v += __shfl_xor_sync(0xffffffffu, v, 2);
    v += __shfl_xor_sync(0xffffffffu, v, 1);
    if (q == 0) g_sc[atom] = v;
}

// ---------------------------------------------------------------------------
// Readout stage B: per-graph softmax over 2500 scores + zero amino.
// ---------------------------------------------------------------------------
__global__ __launch_bounds__(256) void softmax_kernel()
{
    __shared__ float red[256];
    const int b = blockIdx.x;
    const int tid = threadIdx.x;
    float* sc = g_sc + (size_t)b * NG;
    GDS();

    for (int i = tid; i < NA * HDIM; i += 256)
        g_amino[(size_t)b * NA * HDIM + i] = 0.f;

    float m = -1e30f;
    for (int a = tid; a < NG; a += 256) m = fmaxf(m, sc[a]);
    red[tid] = m; __syncthreads();
    for (int s = 128; s; s >>= 1) { if (tid < s) red[tid] = fmaxf(red[tid], red[tid + s]); __syncthreads(); }
    const float mx = red[0]; __syncthreads();

    float ssum = 0.f;
    for (int a = tid; a < NG; a += 256) ssum += expf(sc[a] - mx);
    red[tid] = ssum; __syncthreads();
    for (int s = 128; s; s >>= 1) { if (tid < s) red[tid] += red[tid + s]; __syncthreads(); }
    const float inv = 1.f / red[0];
    __syncthreads();
    for (int a = tid; a < NG; a += 256) sc[a] = expf(sc[a] - mx) * inv;
}

// ---------------------------------------------------------------------------
// Readout stage C: weighted residue accumulation. Grid = NB*50, 64 threads.
// ---------------------------------------------------------------------------
__global__ __launch_bounds__(64) void accum_kernel(const int* __restrict__ labels)
{
    const int b = blockIdx.x / 50;
    const int chunk = blockIdx.x % 50;
    const int d = threadIdx.x;
    const int a0 = chunk * 50;
    GDS();
    const float* h2b = g_h2 + (size_t)b * NG * 64;
    const float* sc = g_sc + (size_t)b * NG;
    const int* lb = labels + (size_t)b * NG;
    float* am = g_amino + (size_t)b * NA * HDIM;

    float acc = 0.f; int cur = -1;
    for (int a = a0; a < a0 + 50; ++a) {
        const int lab = lb[a];
        if (lab != cur) {
            if (cur >= 0) atomicAdd(&am[cur * HDIM + d], acc);
            cur = lab; acc = 0.f;
        }
        acc = fmaf(sc[a], fmaxf(h2b[(size_t)a * 64 + d], 0.f), acc);
    }
    if (cur >= 0) atomicAdd(&am[cur * HDIM + d], acc);
}

// ---------------------------------------------------------------------------
// ARMA root/init terms: 21 GEMMs [1600,159] x [159,128] (+bias), split-N,
// FFMA2 row-packed. Reads amino+aaf directly.
// ---------------------------------------------------------------------------
__global__ __launch_bounds__(256) void armaR_kernel(
    const float* __restrict__ aaf, const float* __restrict__ initw,
    const float* __restrict__ rootw, const float* __restrict__ abias,
    float* __restrict__ z0, float* __restrict__ Rout)
{
    extern __shared__ float smr[];
    float* Xt = smr;                 // [159][68]  Xt[i*68+r]
    float* Ws = smr + FIN * 68;      // [159][64]
    const int blk = blockIdx.x;
    const int c = blk / 50;
    const int rem = blk % 50;
    const int chunk = rem >> 1;
    const int half = rem & 1;
    const int row0 = chunk * 64;
    const int tid = threadIdx.x;

    const float* W;
    const float* bias = nullptr;
    float* out;
    if (c < 3) { W = initw + (size_t)c * FIN * HG; out = z0 + (size_t)c * NB * NA * HG; }
    else {
        const int u = c - 3;
        W = rootw + (size_t)u * FIN * HG;
        bias = abias + (size_t)u * HG;
        out = Rout + (size_t)u * NB * NA * HG;
    }
    {
        const float4* W4 = reinterpret_cast<const float4*>(W);
        float4* Ws4 = reinterpret_cast<float4*>(Ws);
        for (int idx4 = tid; idx4 < FIN * 16; idx4 += 256) {
            const int i = idx4 >> 4, o4 = idx4 & 15;
            Ws4[idx4] = W4[i * 32 + half * 16 + o4];
        }
    }
    GDS();
    {
        for (int idx = tid; idx < 64 * FIN; idx += 256) {
            const int r = idx / FIN, i = idx - r * FIN;
            const int gr = row0 + r;
            const float v = (i < 64) ? g_amino[(size_t)gr * 64 + i]
                                     : aaf[(size_t)gr * AF + (i - 64)];
            Xt[i * 68 + r] = v;
        }
    }
    __syncthreads();

    const int rowg = (tid >> 4) * 4;   // 16 groups of 4 rows (2 pairs)
    const int colg = (tid & 15) * 4;   // 16 groups of 4 cols (within half)
    ull acc[2][4];
    {
        float bv[4] = {0.f, 0.f, 0.f, 0.f};
        if (bias) *reinterpret_cast<float4*>(bv) = *reinterpret_cast<const float4*>(bias + half * 64 + colg);
#pragma unroll
        for (int p = 0; p < 2; ++p)
#pragma unroll
            for (int q = 0; q < 4; ++q) acc[p][q] = pack2(bv[q], bv[q]);
    }
#pragma unroll 4
    for (int i = 0; i < FIN; ++i) {
        const ulonglong2 hp = *reinterpret_cast<const ulonglong2*>(&Xt[i * 68 + rowg]);
        float bv[4];
        *reinterpret_cast<float4*>(bv) = *reinterpret_cast<const float4*>(&Ws[i * 64 + colg]);
        const ull b0 = pack2(bv[0], bv[0]), b1 = pack2(bv[1], bv[1]);
        const ull b2 = pack2(bv[2], bv[2]), b3 = pack2(bv[3], bv[3]);
        acc[0][0] = fma2(hp.x, b0, acc[0][0]); acc[0][1] = fma2(hp.x, b1, acc[0][1]);
        acc[0][2] = fma2(hp.x, b2, acc[0][2]); acc[0][3] = fma2(hp.x, b3, acc[0][3]);
        acc[1][0] = fma2(hp.y, b0, acc[1][0]); acc[1][1] = fma2(hp.y, b1, acc[1][1]);
        acc[1][2] = fma2(hp.y, b2, acc[1][2]); acc[1][3] = fma2(hp.y, b3, acc[1][3]);
    }
#pragma unroll
    for (int p = 0; p < 2; ++p) {
        const float2 u0 = unpack2(acc[p][0]), u1 = unpack2(acc[p][1]);
        const float2 u2 = unpack2(acc[p][2]), u3 = unpack2(acc[p][3]);
        float4 ra; ra.x = u0.x; ra.y = u1.x; ra.z = u2.x; ra.w = u3.x;
        float4 rb; rb.x = u0.y; rb.y = u1.y; rb.z = u2.y; rb.w = u3.y;
        *reinterpret_cast<float4*>(out + (size_t)(row0 + rowg + 2 * p) * HG + half * 64 + colg) = ra;
        *reinterpret_cast<float4*>(out + (size_t)(row0 + rowg + 2 * p + 1) * HG + half * 64 + colg) = rb;
    }
}

// ---------------------------------------------------------------------------
// ARMA recurrence, fused over T. Block per (k, b). 512 threads, FFMA2 GEMM.
// ---------------------------------------------------------------------------
__global__ __launch_bounds__(512) void arma_iter_kernel(
    const float* __restrict__ armaw, const float* __restrict__ z0,
    const float* __restrict__ R, float* __restrict__ outF)
{
    extern __shared__ float sma[];
    float* St  = sma;                    // [128][68]  St[g*68+a]
    float* Y   = sma + 128 * 68;         // [64][128]
    float* Wsm = sma + 128 * 68 + 8192;  // [128][128]
    const int k = blockIdx.x / NB;
    const int b = blockIdx.x % NB;
    const int tid = threadIdx.x;
    GDS();

    const float* Z0p = z0 + ((size_t)k * (NB * NA) + b * NA) * HG;
    const float* R0  = R  + ((size_t)k * (NB * NA) + b * NA) * HG;
    for (int idx = tid; idx < 128 * 64; idx += 512) {
        const int a = idx & 63, g = idx >> 6;
        float v = 0.f;
        if (a < NA) {
            const float zv = (a >= 2) ? Z0p[(a - 1) * HG + g] : 0.f;
            v = fmaxf(zv + R0[a * HG + g], 0.f);
        }
        St[g * 68 + a] = v;
    }

    const int a4 = (tid >> 5) * 4;
    const int g4 = (tid & 31) * 4;

    for (int t = 1; t < TLY; ++t) {
        __syncthreads();
        const float* W = armaw + (size_t)((t - 1) * KST + k) * (HG * HG);
        for (int idx = tid; idx < (HG * HG) / 4; idx += 512)
            reinterpret_cast<float4*>(Wsm)[idx] = reinterpret_cast<const float4*>(W)[idx];
        __syncthreads();

        ull acc[4][2];
#pragma unroll
        for (int a = 0; a < 4; ++a) { acc[a][0] = 0ull; acc[a][1] = 0ull; }
#pragma unroll 8
        for (int kk = 0; kk < HG; ++kk) {
            float sv[4];
            *reinterpret_cast<float4*>(sv) = *reinterpret_cast<const float4*>(&St[kk * 68 + a4]);
            const ulonglong2 wv = *reinterpret_cast<const ulonglong2*>(&Wsm[kk * 128 + g4]);
#pragma unroll
            for (int a = 0; a < 4; ++a) {
                const ull sd = pack2(sv[a], sv[a]);
                acc[a][0] = fma2(sd, wv.x, acc[a][0]);
                acc[a][1] = fma2(sd, wv.y, acc[a][1]);
            }
        }
#pragma unroll
        for (int a = 0; a < 4; ++a) {
            ulonglong2 o; o.x = acc[a][0]; o.y = acc[a][1];
            *reinterpret_cast<ulonglong2*>(&Y[(a4 + a) * 128 + g4]) = o;
        }
        __syncthreads();

        const float* Rt = R + ((size_t)(t * KST + k) * (NB * NA) + b * NA) * HG;
        for (int idx = tid; idx < 128 * 64; idx += 512) {
            const int a = idx & 63, g = idx >> 6;
            float v = 0.f;
            if (a < NA) {
                const float yv = (a >= 2) ? Y[(a - 1) * 128 + g] : 0.f;
                v = fmaxf(yv + Rt[a * HG + g], 0.f);
            }
            St[g * 68 + a] = v;
        }
    }
    __syncthreads();
    float* out = outF + ((size_t)k * NB + b) * (NA * HG);
    for (int idx = tid; idx < NA * HG; idx += 512) {
        const int a = idx >> 7, g = idx & 127;
        out[idx] = St[g * 68 + a];
    }
}

// ---------------------------------------------------------------------------
// Final: g = relu(mean_k outF), residue attention, weighted sum, MLP head.
// ---------------------------------------------------------------------------
__global__ __launch_bounds__(256) void final_kernel(
    const float* __restrict__ outF, const float* __restrict__ attw,
    const float* __restrict__ w1, const float* __restrict__ b1,
    const float* __restrict__ w2, const float* __restrict__ b2,
    const float* __restrict__ w3, const float* __restrict__ b3,
    const float* __restrict__ w4, const float* __restrict__ b4,
    float* __restrict__ outp)
{
    __shared__ float G[NA * HG];
    __shared__ float scw[NA];
    __shared__ float P[HG];
    __shared__ float L1s[64], L2s[32], L3s[16];
    __shared__ float stats[1];
    const int b = blockIdx.x;
    const int tid = threadIdx.x;
    const int wid = tid >> 5, lane = tid & 31;
    GDS();

    const float* f0 = outF + ((size_t)0 * NB + b) * (NA * HG);
    const float* f1 = outF + ((size_t)1 * NB + b) * (NA * HG);
    const float* f2 = outF + ((size_t)2 * NB + b) * (NA * HG);
    for (int idx = tid; idx < NA * HG; idx += 256)
        G[idx] = fmaxf((f0[idx] + f1[idx] + f2[idx]) * (1.f / 3.f), 0.f);
    __syncthreads();

    for (int a = wid; a < NA; a += 8) {
        float v = 0.f;
#pragma unroll
        for (int q = 0; q < 4; ++q) v = fmaf(G[a * HG + lane + q * 32], attw[lane + q * 32], v);
#pragma unroll
        for (int off = 16; off; off >>= 1) v += __shfl_xor_sync(0xffffffffu, v, off);
        if (!lane) scw[a] = v;
    }
    __syncthreads();
    if (tid == 0) {
        float m = -1e30f;
        for (int a = 0; a < NA; ++a) m = fmaxf(m, scw[a]);
        float s = 0.f;
        for (int a = 0; a < NA; ++a) { const float w = expf(scw[a] - m); scw[a] = w; s += w; }
        stats[0] = 1.f / s;
    }
    __syncthreads();
    const float inv = stats[0];
    if (tid < HG) {
        float acc = 0.f;
        for (int a = 0; a < NA; ++a) acc = fmaf(G[a * HG + tid], scw[a], acc);
        P[tid] = acc * inv;
    }
    __syncthreads();
    if (tid < 64) {
        float acc = b1[tid];
        for (int i = 0; i < 128; ++i) acc = fmaf(P[i], w1[i * 64 + tid], acc);
        L1s[tid] = fmaxf(acc, 0.f);
    }
    __syncthreads();
    if (tid < 32) {
        float acc = b2[tid];
        for (int i = 0; i < 64; ++i) acc = fmaf(L1s[i], w2[i * 32 + tid], acc);
        L2s[tid] = fmaxf(acc, 0.f);
    }
    __syncthreads();
    if (tid < 16) {
        float acc = b3[tid];
        for (int i = 0; i < 32; ++i) acc = fmaf(L2s[i], w3[i * 16 + tid], acc);
        L3s[tid] = fmaxf(acc, 0.f);
    }
    __syncthreads();
    if (tid == 0) {
        float acc = b4[0];
        for (int i = 0; i < 16; ++i) acc = fmaf(L3s[i], w4[i], acc);
        outp[b] = acc;
    }
}

// ---------------------------------------------------------------------------
// PDL launch helper.
// ---------------------------------------------------------------------------
template <typename F, typename... Args>
static inline void launch_pdl(F f, dim3 grid, dim3 block, size_t smem, Args... args)
{
    cudaLaunchConfig_t cfg = {};
    cfg.gridDim = grid;
    cfg.blockDim = block;
    cfg.dynamicSmemBytes = smem;
    cudaLaunchAttribute attr[1];
    attr[0].id = cudaLaunchAttributeProgrammaticStreamSerialization;
    attr[0].val.programmaticStreamSerializationAllowed = 1;
    cfg.attrs = attr;
    cfg.numAttrs = 1;
    cudaLaunchKernelEx(&cfg, f, args...);
}

// ---------------------------------------------------------------------------
extern "C" void kernel_launch(void* const* d_in, const int* in_sizes, int n_in,
                              void* d_out, int out_size)
{
    const float* x        = (const float*)d_in[0];
    const int*   eidx     = (const int*)d_in[1];
    const float* eattr    = (const float*)d_in[2];
    const int*   labels   = (const int*)d_in[3];
    const float* aaf      = (const float*)d_in[4];
    const float* w_e1     = (const float*)d_in[5];
    const float* b_e1     = (const float*)d_in[6];
    const float* root1    = (const float*)d_in[7];
    const float* bias1    = (const float*)d_in[8];
    const float* w_e2     = (const float*)d_in[9];
    const float* b_e2     = (const float*)d_in[10];
    const float* root2    = (const float*)d_in[11];
    const float* bias2    = (const float*)d_in[12];
    const float* attwAtom = (const float*)d_in[13];
    const float* initw    = (const float*)d_in[15];
    const float* armaw    = (const float*)d_in[16];
    const float* rootw    = (const float*)d_in[17];
    const float* abias    = (const float*)d_in[18];
    const float* attwAA   = (const float*)d_in[19];
    const float* w1 = (const float*)d_in[21];
    const float* b1 = (const float*)d_in[22];
    const float* w2 = (const float*)d_in[23];
    const float* b2 = (const float*)d_in[24];
    const float* w3 = (const float*)d_in[25];
    const float* b3 = (const float*)d_in[26];
    const float* w4 = (const float*)d_in[27];
    const float* b4 = (const float*)d_in[28];
    float* outp = (float*)d_out;

    float *h1p, *h2p, *z0p, *Rp, *outFp;
    cudaGetSymbolAddress((void**)&h1p, g_h1);
    cudaGetSymbolAddress((void**)&h2p, g_h2);
    cudaGetSymbolAddress((void**)&z0p, g_Z0);
    cudaGetSymbolAddress((void**)&Rp, g_R);
    cudaGetSymbolAddress((void**)&outFp, g_outF);

    const int smemC = (4096 + 8192 + 17 * 64) * sizeof(float);         // 53504
    const int smemR = (FIN * 68 + FIN * 64) * sizeof(float);           // 83952
    const int smemA = (128 * 68 + 8192 + HG * HG) * sizeof(float);     // 133120
    cudaFuncSetAttribute(conv_kernel<false>, cudaFuncAttributeMaxDynamicSharedMemorySize, smemC);
    cudaFuncSetAttribute(conv_kernel<true>,  cudaFuncAttributeMaxDynamicSharedMemorySize, smemC);
    cudaFuncSetAttribute(armaR_kernel, cudaFuncAttributeMaxDynamicSharedMemorySize, smemR);
    cudaFuncSetAttribute(arma_iter_kernel, cudaFuncAttributeMaxDynamicSharedMemorySize, smemA);

    const int* src = eidx;
    const int* dst = eidx + N_EDGES;

    // Zero accumulators (plain launch), then the PDL-chained pipeline.
    zero_kernel<<<1024, 256>>>(h1p, h2p);
    launch_pdl(conv_kernel<false>, dim3(E_TILES + R_TILES), dim3(256), smemC,
               x, src, dst, eattr, w_e1, b_e1, root1, bias1, h1p);
    launch_pdl(conv_kernel<true>, dim3(E_TILES + R_TILES), dim3(256), smemC,
               h1p, src, dst, eattr, w_e2, b_e2, root2, bias2, h2p);
    launch_pdl(score_kernel, dim3(NG * NB / 32), dim3(256), 0, attwAtom);
    launch_pdl(softmax_kernel, dim3(NB), dim3(256), 0);
    launch_pdl(accum_kernel, dim3(NB * 50), dim3(64), 0, labels);
    launch_pdl(armaR_kernel, dim3(21 * 50), dim3(256), (size_t)smemR,
               aaf, initw, rootw, abias, z0p, Rp);
    launch_pdl(arma_iter_kernel, dim3(NB * KST), dim3(512), (size_t)smemA,
               armaw, z0p, Rp, outFp);
    launch_pdl(final_kernel, dim3(NB), dim3(256), 0,
               outFp, attwAA, w1, b1, w2, b2, w3, b3, w4, b4, outp);
}

// round 16
// speedup vs baseline: 1.1421x; 1.1421x over previous
#include <cuda_runtime.h>
#include <math.h>

// Problem constants (fixed by the dataset)
#define N_NODES 80000
#define N_EDGES 64000
#define NB 32
#define NG 2500
#define NA 50
#define HDIM 64
#define EDIM 16
#define HG 128
#define FIN 159   // 64 + 95
#define AF 95
#define KST 3
#define TLY 6

#define E_TILES (N_EDGES / 128)   // 500
#define R_TILES (N_NODES / 64)    // 1250

typedef unsigned long long ull;

__device__ __forceinline__ ull fma2(ull a, ull b, ull c) {
    ull d; asm("fma.rn.f32x2 %0, %1, %2, %3;" : "=l"(d) : "l"(a), "l"(b), "l"(c)); return d;
}
__device__ __forceinline__ ull pack2(float x, float y) {
    ull d; asm("mov.b64 %0, {%1, %2};" : "=l"(d) : "f"(x), "f"(y)); return d;
}
__device__ __forceinline__ float2 unpack2(ull v) {
    float2 r; asm("mov.b64 {%0, %1}, %2;" : "=f"(r.x), "=f"(r.y) : "l"(v)); return r;
}

// PDL: wait for the programmatic-dependency (previous kernel) before touching
// its data. No-op cost if no dependency is attached.
#define GDS() cudaGridDependencySynchronize()

// Scratch (device globals; no runtime allocation allowed)
__device__ float g_h1[N_NODES * HDIM];
__device__ float g_h2[N_NODES * HDIM];
__device__ float g_sc[NB * NG];
__device__ float g_amino[NB * NA * HDIM];
__device__ float g_Z0[KST * NB * NA * HG];
__device__ float g_R[TLY * KST * NB * NA * HG];
__device__ float g_outF[KST * NB * NA * HG];

// ---------------------------------------------------------------------------
// Zero both accumulator buffers (single launch, no upstream dependency).
// ---------------------------------------------------------------------------
__global__ void zero_kernel(float* __restrict__ a, float* __restrict__ b)
{
    const int stride = gridDim.x * blockDim.x;
    const float4 z = make_float4(0.f, 0.f, 0.f, 0.f);
    for (int i = blockIdx.x * blockDim.x + threadIdx.x; i < (N_NODES * HDIM) / 4; i += stride) {
        reinterpret_cast<float4*>(a)[i] = z;
        reinterpret_cast<float4*>(b)[i] = z;
    }
}

// ---------------------------------------------------------------------------
// Fused NNConv: blocks [0, E_TILES) = edge path (128 edges x 64 outs, FFMA2,
// broadcast-B double-buffered in smem, one sync per j); blocks
// [E_TILES, +R_TILES) = root path (64 nodes x 64 outs). Both atomicAdd.
// ---------------------------------------------------------------------------
template <bool RELU>
__global__ __launch_bounds__(256, 2) void conv_kernel(
    const float* __restrict__ h, const int* __restrict__ src,
    const int* __restrict__ dst, const float* __restrict__ ea,
    const float* __restrict__ we, const float* __restrict__ be,
    const float* __restrict__ root, const float* __restrict__ bias,
    float* __restrict__ agg)
{
    extern __shared__ float sm[];
    const int tid = threadIdx.x;
    GDS();

    if (blockIdx.x < E_TILES) {
        // ------------- edge path -------------
        float* Hs  = sm;             // [64][128]  Hs[i*128+e]
        float* Bs  = sm + 8192;      // 2 x [64][64]
        float* Eas = sm + 16384;     // [17][128]

        const int e0 = blockIdx.x * 128;
        {
            const int e = tid & 127;
            const int ge = e0 + e;
            const int half = tid >> 7;   // 0/1
            const int s = src[ge];
            const float4* hp = reinterpret_cast<const float4*>(h + (size_t)s * 64) + half * 8;
#pragma unroll
            for (int r = 0; r < 8; ++r) {
                float4 v = hp[r];
                if (RELU) { v.x = fmaxf(v.x, 0.f); v.y = fmaxf(v.y, 0.f); v.z = fmaxf(v.z, 0.f); v.w = fmaxf(v.w, 0.f); }
                const int i = half * 32 + r * 4;
                Hs[(i + 0) * 128 + e] = v.x; Hs[(i + 1) * 128 + e] = v.y;
                Hs[(i + 2) * 128 + e] = v.z; Hs[(i + 3) * 128 + e] = v.w;
            }
            const float4* ep = reinterpret_cast<const float4*>(ea + (size_t)ge * 16) + half * 2;
            const float4 c0 = ep[0], c1 = ep[1];
            const int jb = half * 8;
            Eas[(jb + 0) * 128 + e] = c0.x; Eas[(jb + 1) * 128 + e] = c0.y;
            Eas[(jb + 2) * 128 + e] = c0.z; Eas[(jb + 3) * 128 + e] = c0.w;
            Eas[(jb + 4) * 128 + e] = c1.x; Eas[(jb + 5) * 128 + e] = c1.y;
            Eas[(jb + 6) * 128 + e] = c1.z; Eas[(jb + 7) * 128 + e] = c1.w;
            if (tid < 128) Eas[16 * 128 + tid] = 1.0f;
        }

        // prefetch B_0 and store into buffer 0 (no cross-thread hazard)
        float4 breg[4];
        {
            const float4* Bsrc = reinterpret_cast<const float4*>(we);
#pragma unroll
            for (int r = 0; r < 4; ++r) breg[r] = Bsrc[tid + r * 256];
            float4* d = reinterpret_cast<float4*>(Bs);
#pragma unroll
            for (int r = 0; r < 4; ++r) d[tid + r * 256] = breg[r];
        }
        __syncthreads();   // Hs/Eas/B0 visible

        const int eg = (tid >> 4) * 8;    // 16 edge-groups of 8
        const int og = (tid & 15) * 4;    // 16 out-groups of 4

        ull acc[4][4];
#pragma unroll
        for (int a = 0; a < 4; ++a)
#pragma unroll
            for (int q = 0; q < 4; ++q) acc[a][q] = 0ull;

        for (int j = 0; j < 17; ++j) {
            if (j < 16) {
                const float4* Bsrc = reinterpret_cast<const float4*>(j < 15 ? we + (size_t)(j + 1) * 4096 : be);
#pragma unroll
                for (int r = 0; r < 4; ++r) breg[r] = Bsrc[tid + r * 256];
            }
            const float* Bcur = Bs + (j & 1) * 4096;

            ull t[4][4];
#pragma unroll
            for (int a = 0; a < 4; ++a)
#pragma unroll
                for (int q = 0; q < 4; ++q) t[a][q] = 0ull;

#pragma unroll 8
            for (int i = 0; i < 64; ++i) {
                const ulonglong2 h01 = *reinterpret_cast<const ulonglong2*>(&Hs[i * 128 + eg]);
                const ulonglong2 h23 = *reinterpret_cast<const ulonglong2*>(&Hs[i * 128 + eg + 4]);
                const float4 bv = *reinterpret_cast<const float4*>(&Bcur[i * 64 + og]);
                const ull b0 = pack2(bv.x, bv.x), b1 = pack2(bv.y, bv.y);
                const ull b2 = pack2(bv.z, bv.z), b3 = pack2(bv.w, bv.w);
                t[0][0] = fma2(h01.x, b0, t[0][0]); t[0][1] = fma2(h01.x, b1, t[0][1]);
                t[0][2] = fma2(h01.x, b2, t[0][2]); t[0][3] = fma2(h01.x, b3, t[0][3]);
                t[1][0] = fma2(h01.y, b0, t[1][0]); t[1][1] = fma2(h01.y, b1, t[1][1]);
                t[1][2] = fma2(h01.y, b2, t[1][2]); t[1][3] = fma2(h01.y, b3, t[1][3]);
                t[2][0] = fma2(h23.x, b0, t[2][0]); t[2][1] = fma2(h23.x, b1, t[2][1]);
                t[2][2] = fma2(h23.x, b2, t[2][2]); t[2][3] = fma2(h23.x, b3, t[2][3]);
                t[3][0] = fma2(h23.y, b0, t[3][0]); t[3][1] = fma2(h23.y, b1, t[3][1]);
                t[3][2] = fma2(h23.y, b2, t[3][2]); t[3][3] = fma2(h23.y, b3, t[3][3]);
            }
            const ulonglong2 c01 = *reinterpret_cast<const ulonglong2*>(&Eas[j * 128 + eg]);
            const ulonglong2 c23 = *reinterpret_cast<const ulonglong2*>(&Eas[j * 128 + eg + 4]);
#pragma unroll
            for (int q = 0; q < 4; ++q) {
                acc[0][q] = fma2(c01.x, t[0][q], acc[0][q]);
                acc[1][q] = fma2(c01.y, t[1][q], acc[1][q]);
                acc[2][q] = fma2(c23.x, t[2][q], acc[2][q]);
                acc[3][q] = fma2(c23.y, t[3][q], acc[3][q]);
            }
            if (j < 16) {
                float4* d = reinterpret_cast<float4*>(Bs + ((j + 1) & 1) * 4096);
#pragma unroll
                for (int r = 0; r < 4; ++r) d[tid + r * 256] = breg[r];
            }
            __syncthreads();
        }

#pragma unroll
        for (int a = 0; a < 4; ++a) {
            const int d0 = dst[e0 + eg + 2 * a];
            const int d1 = dst[e0 + eg + 2 * a + 1];
            float* p0 = agg + (size_t)d0 * 64 + og;
            float* p1 = agg + (size_t)d1 * 64 + og;
#pragma unroll
            for (int q = 0; q < 4; ++q) {
                const float2 v = unpack2(acc[a][q]);
                atomicAdd(p0 + q, v.x);
                atomicAdd(p1 + q, v.y);
            }
        }
    } else {
        // ------------- root path -------------
        float* Hs = sm;           // [64][64]  Hs[i*64+node]
        float* Bs = sm + 4096;    // [64][64]
        const int n0 = (blockIdx.x - E_TILES) * 64;
        {
            const int e = tid & 63;
            const float4* hp = reinterpret_cast<const float4*>(h + (size_t)(n0 + e) * 64);
#pragma unroll
            for (int r = 0; r < 4; ++r) {
                const int i4 = (tid >> 6) + r * 4;
                float4 v = hp[i4];
                if (RELU) { v.x = fmaxf(v.x, 0.f); v.y = fmaxf(v.y, 0.f); v.z = fmaxf(v.z, 0.f); v.w = fmaxf(v.w, 0.f); }
                Hs[(i4 * 4 + 0) * 64 + e] = v.x; Hs[(i4 * 4 + 1) * 64 + e] = v.y;
                Hs[(i4 * 4 + 2) * 64 + e] = v.z; Hs[(i4 * 4 + 3) * 64 + e] = v.w;
            }
        }
        for (int idx = tid; idx < 1024; idx += 256)
            reinterpret_cast<float4*>(Bs)[idx] = reinterpret_cast<const float4*>(root)[idx];
        __syncthreads();

        const int ty4 = (tid >> 4) * 4;
        const int tx4 = (tid & 15) * 4;
        float acc[4][4];
        const float4 bb = *reinterpret_cast<const float4*>(bias + tx4);
#pragma unroll
        for (int a = 0; a < 4; ++a) { acc[a][0] = bb.x; acc[a][1] = bb.y; acc[a][2] = bb.z; acc[a][3] = bb.w; }
#pragma unroll
        for (int i = 0; i < 64; ++i) {
            float hv[4], bv[4];
            *reinterpret_cast<float4*>(hv) = *reinterpret_cast<const float4*>(&Hs[i * 64 + ty4]);
            *reinterpret_cast<float4*>(bv) = *reinterpret_cast<const float4*>(&Bs[i * 64 + tx4]);
#pragma unroll
            for (int a = 0; a < 4; ++a)
#pragma unroll
                for (int q = 0; q < 4; ++q) acc[a][q] = fmaf(hv[a], bv[q], acc[a][q]);
        }
#pragma unroll
        for (int a = 0; a < 4; ++a) {
            float* p = agg + (size_t)(n0 + ty4 + a) * 64 + tx4;
#pragma unroll
            for (int q = 0; q < 4; ++q) atomicAdd(p + q, acc[a][q]);
        }
    }
}

// ---------------------------------------------------------------------------
// Readout stage A: per-atom attention scores. Grid = 2500, 32 atoms/block.
// ---------------------------------------------------------------------------
__global__ __launch_bounds__(256) void score_kernel(const float* __restrict__ attw)
{
    const int tid = threadIdx.x;
    const int q = tid & 7;
    const int atom = blockIdx.x * 32 + (tid >> 3);
    GDS();
    const float4 aw0 = *reinterpret_cast<const float4*>(attw + q * 8);
    const float4 aw1 = *reinterpret_cast<const float4*>(attw + q * 8 + 4);
    const float* hr = g_h2 + (size_t)atom * 64 + q * 8;
    const float4 u0 = *reinterpret_cast<const float4*>(hr);
    const float4 u1 = *reinterpret_cast<const float4*>(hr + 4);
    float v = fmaxf(u0.x, 0.f) * aw0.x + fmaxf(u0.y, 0.f) * aw0.y +
              fmaxf(u0.z, 0.f) * aw0.z + fmaxf(u0.w, 0.f) * aw0.w +
              fmaxf(u1.x, 0.f) * aw1.x + fmaxf(u1.y, 0.f) * aw1.y +
              fmaxf(u1.z, 0.f) * aw1.z + fmaxf(u1.w, 0.f) * aw1.w;
    v += __shfl_xor_sync(0xffffffffu, v, 4);
    v += __shfl_xor_sync(0xffffffffu, v, 2);
    v += __shfl_xor_sync(0xffffffffu, v, 1);
    if (q == 0) g_sc[atom] = v;
}

// ---------------------------------------------------------------------------
// Readout stage B: per-graph softmax over 2500 scores + zero amino.
// ---------------------------------------------------------------------------
__global__ __launch_bounds__(256) void softmax_kernel()
{
    __shared__ float red[256];
    const int b = blockIdx.x;
    const int tid = threadIdx.x;
    float* sc = g_sc + (size_t)b * NG;
    GDS();

    for (int i = tid; i < NA * HDIM; i += 256)
        g_amino[(size_t)b * NA * HDIM + i] = 0.f;

    float m = -1e30f;
    for (int a = tid; a < NG; a += 256) m = fmaxf(m, sc[a]);
    red[tid] = m; __syncthreads();
    for (int s = 128; s; s >>= 1) { if (tid < s) red[tid] = fmaxf(red[tid], red[tid + s]); __syncthreads(); }
    const float mx = red[0]; __syncthreads();

    float ssum = 0.f;
    for (int a = tid; a < NG; a += 256) ssum += expf(sc[a] - mx);
    red[tid] = ssum; __syncthreads();
    for (int s = 128; s; s >>= 1) { if (tid < s) red[tid] += red[tid + s]; __syncthreads(); }
    const float inv = 1.f / red[0];
    __syncthreads();
    for (int a = tid; a < NG; a += 256) sc[a] = expf(sc[a] - mx) * inv;
}

// ---------------------------------------------------------------------------
// Readout stage C: weighted residue accumulation. Grid = NB*50, 64 threads,
// 50 contiguous atoms per block; run-length by label, atomics at boundaries.
// ---------------------------------------------------------------------------
__global__ __launch_bounds__(64) void accum_kernel(const int* __restrict__ labels)
{
    const int b = blockIdx.x / 50;
    const int chunk = blockIdx.x % 50;
    const int d = threadIdx.x;
    const int a0 = chunk * 50;
    GDS();
    const float* h2b = g_h2 + (size_t)b * NG * 64;
    const float* sc = g_sc + (size_t)b * NG;
    const int* lb = labels + (size_t)b * NG;
    float* am = g_amino + (size_t)b * NA * HDIM;

    float acc = 0.f; int cur = -1;
    for (int a = a0; a < a0 + 50; ++a) {
        const int lab = lb[a];
        if (lab != cur) {
            if (cur >= 0) atomicAdd(&am[cur * HDIM + d], acc);
            cur = lab; acc = 0.f;
        }
        acc = fmaf(sc[a], fmaxf(h2b[(size_t)a * 64 + d], 0.f), acc);
    }
    if (cur >= 0) atomicAdd(&am[cur * HDIM + d], acc);
}

// ---------------------------------------------------------------------------
// ARMA root/init terms: 21 GEMMs [1600,159] x [159,128] (+bias), split-N,
// FFMA2 row-packed. Reads amino+aaf directly (xi row gr = amino[gr] ‖ aaf[gr]).
// ---------------------------------------------------------------------------
__global__ __launch_bounds__(256) void armaR_kernel(
    const float* __restrict__ aaf, const float* __restrict__ initw,
    const float* __restrict__ rootw, const float* __restrict__ abias,
    float* __restrict__ z0, float* __restrict__ Rout)
{
    extern __shared__ float smr[];
    float* Xt = smr;                 // [159][68]  Xt[i*68+r]
    float* Ws = smr + FIN * 68;      // [159][64]
    const int blk = blockIdx.x;
    const int c = blk / 50;
    const int rem = blk % 50;
    const int chunk = rem >> 1;
    const int half = rem & 1;
    const int row0 = chunk * 64;
    const int tid = threadIdx.x;

    const float* W;
    const float* bias = nullptr;
    float* out;
    if (c < 3) { W = initw + (size_t)c * FIN * HG; out = z0 + (size_t)c * NB * NA * HG; }
    else {
        const int u = c - 3;
        W = rootw + (size_t)u * FIN * HG;
        bias = abias + (size_t)u * HG;
        out = Rout + (size_t)u * NB * NA * HG;
    }
    {
        const float4* W4 = reinterpret_cast<const float4*>(W);
        float4* Ws4 = reinterpret_cast<float4*>(Ws);
        for (int idx4 = tid; idx4 < FIN * 16; idx4 += 256) {
            const int i = idx4 >> 4, o4 = idx4 & 15;
            Ws4[idx4] = W4[i * 32 + half * 16 + o4];
        }
    }
    GDS();
    {
        for (int idx = tid; idx < 64 * FIN; idx += 256) {
            const int r = idx / FIN, i = idx - r * FIN;
            const int gr = row0 + r;
            const float v = (i < 64) ? g_amino[(size_t)gr * 64 + i]
                                     : aaf[(size_t)gr * AF + (i - 64)];
            Xt[i * 68 + r] = v;
        }
    }
    __syncthreads();

    const int rowg = (tid >> 4) * 4;   // 16 groups of 4 rows (2 pairs)
    const int colg = (tid & 15) * 4;   // 16 groups of 4 cols (within half)
    ull acc[2][4];
    {
        float bv[4] = {0.f, 0.f, 0.f, 0.f};
        if (bias) *reinterpret_cast<float4*>(bv) = *reinterpret_cast<const float4*>(bias + half * 64 + colg);
#pragma unroll
        for (int p = 0; p < 2; ++p)
#pragma unroll
            for (int q = 0; q < 4; ++q) acc[p][q] = pack2(bv[q], bv[q]);
    }
#pragma unroll 4
    for (int i = 0; i < FIN; ++i) {
        const ulonglong2 hp = *reinterpret_cast<const ulonglong2*>(&Xt[i * 68 + rowg]);
        float bv[4];
        *reinterpret_cast<float4*>(bv) = *reinterpret_cast<const float4*>(&Ws[i * 64 + colg]);
        const ull b0 = pack2(bv[0], bv[0]), b1 = pack2(bv[1], bv[1]);
        const ull b2 = pack2(bv[2], bv[2]), b3 = pack2(bv[3], bv[3]);
        acc[0][0] = fma2(hp.x, b0, acc[0][0]); acc[0][1] = fma2(hp.x, b1, acc[0][1]);
        acc[0][2] = fma2(hp.x, b2, acc[0][2]); acc[0][3] = fma2(hp.x, b3, acc[0][3]);
        acc[1][0] = fma2(hp.y, b0, acc[1][0]); acc[1][1] = fma2(hp.y, b1, acc[1][1]);
        acc[1][2] = fma2(hp.y, b2, acc[1][2]); acc[1][3] = fma2(hp.y, b3, acc[1][3]);
    }
#pragma unroll
    for (int p = 0; p < 2; ++p) {
        const float2 u0 = unpack2(acc[p][0]), u1 = unpack2(acc[p][1]);
        const float2 u2 = unpack2(acc[p][2]), u3 = unpack2(acc[p][3]);
        float4 ra; ra.x = u0.x; ra.y = u1.x; ra.z = u2.x; ra.w = u3.x;
        float4 rb; rb.x = u0.y; rb.y = u1.y; rb.z = u2.y; rb.w = u3.y;
        *reinterpret_cast<float4*>(out + (size_t)(row0 + rowg + 2 * p) * HG + half * 64 + colg) = ra;
        *reinterpret_cast<float4*>(out + (size_t)(row0 + rowg + 2 * p + 1) * HG + half * 64 + colg) = rb;
    }
}

// ---------------------------------------------------------------------------
// ARMA recurrence, fused over T. Block per (k, b). 512 threads, FFMA2 GEMM.
// ---------------------------------------------------------------------------
__global__ __launch_bounds__(512) void arma_iter_kernel(
    const float* __restrict__ armaw, const float* __restrict__ z0,
    const float* __restrict__ R, float* __restrict__ outF)
{
    extern __shared__ float sma[];
    float* St  = sma;                    // [128][68]  St[g*68+a]
    float* Y   = sma + 128 * 68;         // [64][128]
    float* Wsm = sma + 128 * 68 + 8192;  // [128][128]
    const int k = blockIdx.x / NB;
    const int b = blockIdx.x % NB;
    const int tid = threadIdx.x;
    GDS();

    const float* Z0p = z0 + ((size_t)k * (NB * NA) + b * NA) * HG;
    const float* R0  = R  + ((size_t)k * (NB * NA) + b * NA) * HG;
    for (int idx = tid; idx < 128 * 64; idx += 512) {
        const int a = idx & 63, g = idx >> 6;
        float v = 0.f;
        if (a < NA) {
            const float zv = (a >= 2) ? Z0p[(a - 1) * HG + g] : 0.f;
            v = fmaxf(zv + R0[a * HG + g], 0.f);
        }
        St[g * 68 + a] = v;
    }

    const int a4 = (tid >> 5) * 4;
    const int g4 = (tid & 31) * 4;

    for (int t = 1; t < TLY; ++t) {
        __syncthreads();
        const float* W = armaw + (size_t)((t - 1) * KST + k) * (HG * HG);
        for (int idx = tid; idx < (HG * HG) / 4; idx += 512)
            reinterpret_cast<float4*>(Wsm)[idx] = reinterpret_cast<const float4*>(W)[idx];
        __syncthreads();

        ull acc[4][2];
#pragma unroll
        for (int a = 0; a < 4; ++a) { acc[a][0] = 0ull; acc[a][1] = 0ull; }
#pragma unroll 8
        for (int kk = 0; kk < HG; ++kk) {
            float sv[4];
            *reinterpret_cast<float4*>(sv) = *reinterpret_cast<const float4*>(&St[kk * 68 + a4]);
            const ulonglong2 wv = *reinterpret_cast<const ulonglong2*>(&Wsm[kk * 128 + g4]);
#pragma unroll
            for (int a = 0; a < 4; ++a) {
                const ull sd = pack2(sv[a], sv[a]);
                acc[a][0] = fma2(sd, wv.x, acc[a][0]);
                acc[a][1] = fma2(sd, wv.y, acc[a][1]);
            }
        }
#pragma unroll
        for (int a = 0; a < 4; ++a) {
            ulonglong2 o; o.x = acc[a][0]; o.y = acc[a][1];
            *reinterpret_cast<ulonglong2*>(&Y[(a4 + a) * 128 + g4]) = o;
        }
        __syncthreads();

        const float* Rt = R + ((size_t)(t * KST + k) * (NB * NA) + b * NA) * HG;
        for (int idx = tid; idx < 128 * 64; idx += 512) {
            const int a = idx & 63, g = idx >> 6;
            float v = 0.f;
            if (a < NA) {
                const float yv = (a >= 2) ? Y[(a - 1) * 128 + g] : 0.f;
                v = fmaxf(yv + Rt[a * HG + g], 0.f);
            }
            St[g * 68 + a] = v;
        }
    }
    __syncthreads();
    float* out = outF + ((size_t)k * NB + b) * (NA * HG);
    for (int idx = tid; idx < NA * HG; idx += 512) {
        const int a = idx >> 7, g = idx & 127;
        out[idx] = St[g * 68 + a];
    }
}

// ---------------------------------------------------------------------------
// Final: g = relu(mean_k outF), residue attention, weighted sum, MLP head.
// ---------------------------------------------------------------------------
__global__ __launch_bounds__(256) void final_kernel(
    const float* __restrict__ outF, const float* __restrict__ attw,
    const float* __restrict__ w1, const float* __restrict__ b1,
    const float* __restrict__ w2, const float* __restrict__ b2,
    const float* __restrict__ w3, const float* __restrict__ b3,
    const float* __restrict__ w4, const float* __restrict__ b4,
    float* __restrict__ outp)
{
    __shared__ float G[NA * HG];
    __shared__ float scw[NA];
    __shared__ float P[HG];
    __shared__ float L1s[64], L2s[32], L3s[16];
    __shared__ float stats[1];
    const int b = blockIdx.x;
    const int tid = threadIdx.x;
    const int wid = tid >> 5, lane = tid & 31;
    GDS();

    const float* f0 = outF + ((size_t)0 * NB + b) * (NA * HG);
    const float* f1 = outF + ((size_t)1 * NB + b) * (NA * HG);
    const float* f2 = outF + ((size_t)2 * NB + b) * (NA * HG);
    for (int idx = tid; idx < NA * HG; idx += 256)
        G[idx] = fmaxf((f0[idx] + f1[idx] + f2[idx]) * (1.f / 3.f), 0.f);
    __syncthreads();

    for (int a = wid; a < NA; a += 8) {
        float v = 0.f;
#pragma unroll
        for (int q = 0; q < 4; ++q) v = fmaf(G[a * HG + lane + q * 32], attw[lane + q * 32], v);
#pragma unroll
        for (int off = 16; off; off >>= 1) v += __shfl_xor_sync(0xffffffffu, v, off);
        if (!lane) scw[a] = v;
    }
    __syncthreads();
    if (tid == 0) {
        float m = -1e30f;
        for (int a = 0; a < NA; ++a) m = fmaxf(m, scw[a]);
        float s = 0.f;
        for (int a = 0; a < NA; ++a) { const float w = expf(scw[a] - m); scw[a] = w; s += w; }
        stats[0] = 1.f / s;
    }
    __syncthreads();
    const float inv = stats[0];
    if (tid < HG) {
        float acc = 0.f;
        for (int a = 0; a < NA; ++a) acc = fmaf(G[a * HG + tid], scw[a], acc);
        P[tid] = acc * inv;
    }
    __syncthreads();
    if (tid < 64) {
        float acc = b1[tid];
        for (int i = 0; i < 128; ++i) acc = fmaf(P[i], w1[i * 64 + tid], acc);
        L1s[tid] = fmaxf(acc, 0.f);
    }
    __syncthreads();
    if (tid < 32) {
        float acc = b2[tid];
        for (int i = 0; i < 64; ++i) acc = fmaf(L1s[i], w2[i * 32 + tid], acc);
        L2s[tid] = fmaxf(acc, 0.f);
    }
    __syncthreads();
    if (tid < 16) {
        float acc = b3[tid];
        for (int i = 0; i < 32; ++i) acc = fmaf(L2s[i], w3[i * 16 + tid], acc);
        L3s[tid] = fmaxf(acc, 0.f);
    }
    __syncthreads();
    if (tid == 0) {
        float acc = b4[0];
        for (int i = 0; i < 16; ++i) acc = fmaf(L3s[i], w4[i], acc);
        outp[b] = acc;
    }
}

// ---------------------------------------------------------------------------
// PDL launch helper: secondary may begin while predecessor drains; the kernel
// gates dependent reads via cudaGridDependencySynchronize().
// ---------------------------------------------------------------------------
template <typename F, typename... Args>
static inline void launch_pdl(F f, dim3 grid, dim3 block, size_t smem, Args... args)
{
    cudaLaunchConfig_t cfg = {};
    cfg.gridDim = grid;
    cfg.blockDim = block;
    cfg.dynamicSmemBytes = smem;
    cudaLaunchAttribute attr[1];
    attr[0].id = cudaLaunchAttributeProgrammaticStreamSerialization;
    attr[0].val.programmaticStreamSerializationAllowed = 1;
    cfg.attrs = attr;
    cfg.numAttrs = 1;
    cudaLaunchKernelEx(&cfg, f, args...);
}

// ---------------------------------------------------------------------------
extern "C" void kernel_launch(void* const* d_in, const int* in_sizes, int n_in,
                              void* d_out, int out_size)
{
    const float* x        = (const float*)d_in[0];
    const int*   eidx     = (const int*)d_in[1];
    const float* eattr    = (const float*)d_in[2];
    const int*   labels   = (const int*)d_in[3];
    const float* aaf      = (const float*)d_in[4];
    const float* w_e1     = (const float*)d_in[5];
    const float* b_e1     = (const float*)d_in[6];
    const float* root1    = (const float*)d_in[7];
    const float* bias1    = (const float*)d_in[8];
    const float* w_e2     = (const float*)d_in[9];
    const float* b_e2     = (const float*)d_in[10];
    const float* root2    = (const float*)d_in[11];
    const float* bias2    = (const float*)d_in[12];
    const float* attwAtom = (const float*)d_in[13];
    const float* initw    = (const float*)d_in[15];
    const float* armaw    = (const float*)d_in[16];
    const float* rootw    = (const float*)d_in[17];
    const float* abias    = (const float*)d_in[18];
    const float* attwAA   = (const float*)d_in[19];
    const float* w1 = (const float*)d_in[21];
    const float* b1 = (const float*)d_in[22];
    const float* w2 = (const float*)d_in[23];
    const float* b2 = (const float*)d_in[24];
    const float* w3 = (const float*)d_in[25];
    const float* b3 = (const float*)d_in[26];
    const float* w4 = (const float*)d_in[27];
    const float* b4 = (const float*)d_in[28];
    float* outp = (float*)d_out;

    float *h1p, *h2p, *z0p, *Rp, *outFp;
    cudaGetSymbolAddress((void**)&h1p, g_h1);
    cudaGetSymbolAddress((void**)&h2p, g_h2);
    cudaGetSymbolAddress((void**)&z0p, g_Z0);
    cudaGetSymbolAddress((void**)&Rp, g_R);
    cudaGetSymbolAddress((void**)&outFp, g_outF);

    const int smemC = (8192 + 8192 + 17 * 128) * sizeof(float);        // 74240
    const int smemR = (FIN * 68 + FIN * 64) * sizeof(float);           // 83952
    const int smemA = (128 * 68 + 8192 + HG * HG) * sizeof(float);     // 133120
    cudaFuncSetAttribute(conv_kernel<false>, cudaFuncAttributeMaxDynamicSharedMemorySize, smemC);
    cudaFuncSetAttribute(conv_kernel<true>,  cudaFuncAttributeMaxDynamicSharedMemorySize, smemC);
    cudaFuncSetAttribute(armaR_kernel, cudaFuncAttributeMaxDynamicSharedMemorySize, smemR);
    cudaFuncSetAttribute(arma_iter_kernel, cudaFuncAttributeMaxDynamicSharedMemorySize, smemA);

    const int* src = eidx;
    const int* dst = eidx + N_EDGES;

    // Zero accumulators (plain launch), then the PDL-chained pipeline.
    zero_kernel<<<1024, 256>>>(h1p, h2p);
    launch_pdl(conv_kernel<false>, dim3(E_TILES + R_TILES), dim3(256), smemC,
               x, src, dst, eattr, w_e1, b_e1, root1, bias1, h1p);
    launch_pdl(conv_kernel<true>, dim3(E_TILES + R_TILES), dim3(256), smemC,
               h1p, src, dst, eattr, w_e2, b_e2, root2, bias2, h2p);
    launch_pdl(score_kernel, dim3(NG * NB / 32), dim3(256), 0, attwAtom);
    launch_pdl(softmax_kernel, dim3(NB), dim3(256), 0);
    launch_pdl(accum_kernel, dim3(NB * 50), dim3(64), 0, labels);
    launch_pdl(armaR_kernel, dim3(21 * 50), dim3(256), (size_t)smemR,
               aaf, initw, rootw, abias, z0p, Rp);
    launch_pdl(arma_iter_kernel, dim3(NB * KST), dim3(512), (size_t)smemA,
               armaw, z0p, Rp, outFp);
    launch_pdl(final_kernel, dim3(NB), dim3(256), 0,
               outFp, attwAA, w1, b1, w2, b2, w3, b3, w4, b4, outp);
}

// round 17
// speedup vs baseline: 1.1745x; 1.0283x over previous
#include <cuda_runtime.h>
#include <math.h>

// Problem constants (fixed by the dataset)
#define N_NODES 80000
#define N_EDGES 64000
#define NB 32
#define NG 2500
#define NA 50
#define HDIM 64
#define EDIM 16
#define HG 128
#define FIN 159   // 64 + 95
#define AF 95
#define KST 3
#define TLY 6

#define E_TILES (N_EDGES / 128)   // 500
#define R_TILES (N_NODES / 64)    // 1250

typedef unsigned long long ull;

__device__ __forceinline__ ull fma2(ull a, ull b, ull c) {
    ull d; asm("fma.rn.f32x2 %0, %1, %2, %3;" : "=l"(d) : "l"(a), "l"(b), "l"(c)); return d;
}
__device__ __forceinline__ ull pack2(float x, float y) {
    ull d; asm("mov.b64 %0, {%1, %2};" : "=l"(d) : "f"(x), "f"(y)); return d;
}
__device__ __forceinline__ float2 unpack2(ull v) {
    float2 r; asm("mov.b64 {%0, %1}, %2;" : "=f"(r.x), "=f"(r.y) : "l"(v)); return r;
}
// Vectorized global reduction: 4 contiguous float adds in one instruction.
__device__ __forceinline__ void red_add_v4(float* p, float x, float y, float z, float w) {
    asm volatile("red.global.add.v4.f32 [%0], {%1, %2, %3, %4};"
                 :: "l"(p), "f"(x), "f"(y), "f"(z), "f"(w) : "memory");
}

// PDL: wait for the programmatic-dependency (previous kernel) before touching
// its data. No-op cost if no dependency is attached.
#define GDS() cudaGridDependencySynchronize()

// Scratch (device globals; no runtime allocation allowed)
__device__ float g_h1[N_NODES * HDIM];
__device__ float g_h2[N_NODES * HDIM];
__device__ float g_sc[NB * NG];
__device__ float g_amino[NB * NA * HDIM];
__device__ float g_Z0[KST * NB * NA * HG];
__device__ float g_R[TLY * KST * NB * NA * HG];
__device__ float g_outF[KST * NB * NA * HG];

// ---------------------------------------------------------------------------
// Zero both accumulator buffers (single launch, no upstream dependency).
// ---------------------------------------------------------------------------
__global__ void zero_kernel(float* __restrict__ a, float* __restrict__ b)
{
    const int stride = gridDim.x * blockDim.x;
    const float4 z = make_float4(0.f, 0.f, 0.f, 0.f);
    for (int i = blockIdx.x * blockDim.x + threadIdx.x; i < (N_NODES * HDIM) / 4; i += stride) {
        reinterpret_cast<float4*>(a)[i] = z;
        reinterpret_cast<float4*>(b)[i] = z;
    }
}

// ---------------------------------------------------------------------------
// Fused NNConv: blocks [0, E_TILES) = edge path (128 edges x 64 outs, FFMA2,
// broadcast-B double-buffered in smem, one sync per j); blocks
// [E_TILES, +R_TILES) = root path (64 nodes x 64 outs). Both scatter with
// red.global.add.v4.f32 into the zeroed agg.
// ---------------------------------------------------------------------------
template <bool RELU>
__global__ __launch_bounds__(256, 2) void conv_kernel(
    const float* __restrict__ h, const int* __restrict__ src,
    const int* __restrict__ dst, const float* __restrict__ ea,
    const float* __restrict__ we, const float* __restrict__ be,
    const float* __restrict__ root, const float* __restrict__ bias,
    float* __restrict__ agg)
{
    extern __shared__ float sm[];
    const int tid = threadIdx.x;
    GDS();

    if (blockIdx.x < E_TILES) {
        // ------------- edge path -------------
        float* Hs  = sm;             // [64][128]  Hs[i*128+e]
        float* Bs  = sm + 8192;      // 2 x [64][64]
        float* Eas = sm + 16384;     // [17][128]

        const int e0 = blockIdx.x * 128;
        {
            const int e = tid & 127;
            const int ge = e0 + e;
            const int half = tid >> 7;   // 0/1
            const int s = src[ge];
            const float4* hp = reinterpret_cast<const float4*>(h + (size_t)s * 64) + half * 8;
#pragma unroll
            for (int r = 0; r < 8; ++r) {
                float4 v = hp[r];
                if (RELU) { v.x = fmaxf(v.x, 0.f); v.y = fmaxf(v.y, 0.f); v.z = fmaxf(v.z, 0.f); v.w = fmaxf(v.w, 0.f); }
                const int i = half * 32 + r * 4;
                Hs[(i + 0) * 128 + e] = v.x; Hs[(i + 1) * 128 + e] = v.y;
                Hs[(i + 2) * 128 + e] = v.z; Hs[(i + 3) * 128 + e] = v.w;
            }
            const float4* ep = reinterpret_cast<const float4*>(ea + (size_t)ge * 16) + half * 2;
            const float4 c0 = ep[0], c1 = ep[1];
            const int jb = half * 8;
            Eas[(jb + 0) * 128 + e] = c0.x; Eas[(jb + 1) * 128 + e] = c0.y;
            Eas[(jb + 2) * 128 + e] = c0.z; Eas[(jb + 3) * 128 + e] = c0.w;
            Eas[(jb + 4) * 128 + e] = c1.x; Eas[(jb + 5) * 128 + e] = c1.y;
            Eas[(jb + 6) * 128 + e] = c1.z; Eas[(jb + 7) * 128 + e] = c1.w;
            if (tid < 128) Eas[16 * 128 + tid] = 1.0f;
        }

        // prefetch B_0 and store into buffer 0 (no cross-thread hazard)
        float4 breg[4];
        {
            const float4* Bsrc = reinterpret_cast<const float4*>(we);
#pragma unroll
            for (int r = 0; r < 4; ++r) breg[r] = Bsrc[tid + r * 256];
            float4* d = reinterpret_cast<float4*>(Bs);
#pragma unroll
            for (int r = 0; r < 4; ++r) d[tid + r * 256] = breg[r];
        }
        __syncthreads();   // Hs/Eas/B0 visible

        const int eg = (tid >> 4) * 8;    // 16 edge-groups of 8
        const int og = (tid & 15) * 4;    // 16 out-groups of 4

        ull acc[4][4];
#pragma unroll
        for (int a = 0; a < 4; ++a)
#pragma unroll
            for (int q = 0; q < 4; ++q) acc[a][q] = 0ull;

        for (int j = 0; j < 17; ++j) {
            if (j < 16) {
                const float4* Bsrc = reinterpret_cast<const float4*>(j < 15 ? we + (size_t)(j + 1) * 4096 : be);
#pragma unroll
                for (int r = 0; r < 4; ++r) breg[r] = Bsrc[tid + r * 256];
            }
            const float* Bcur = Bs + (j & 1) * 4096;

            ull t[4][4];
#pragma unroll
            for (int a = 0; a < 4; ++a)
#pragma unroll
                for (int q = 0; q < 4; ++q) t[a][q] = 0ull;

#pragma unroll 8
            for (int i = 0; i < 64; ++i) {
                const ulonglong2 h01 = *reinterpret_cast<const ulonglong2*>(&Hs[i * 128 + eg]);
                const ulonglong2 h23 = *reinterpret_cast<const ulonglong2*>(&Hs[i * 128 + eg + 4]);
                const float4 bv = *reinterpret_cast<const float4*>(&Bcur[i * 64 + og]);
                const ull b0 = pack2(bv.x, bv.x), b1 = pack2(bv.y, bv.y);
                const ull b2 = pack2(bv.z, bv.z), b3 = pack2(bv.w, bv.w);
                t[0][0] = fma2(h01.x, b0, t[0][0]); t[0][1] = fma2(h01.x, b1, t[0][1]);
                t[0][2] = fma2(h01.x, b2, t[0][2]); t[0][3] = fma2(h01.x, b3, t[0][3]);
                t[1][0] = fma2(h01.y, b0, t[1][0]); t[1][1] = fma2(h01.y, b1, t[1][1]);
                t[1][2] = fma2(h01.y, b2, t[1][2]); t[1][3] = fma2(h01.y, b3, t[1][3]);
                t[2][0] = fma2(h23.x, b0, t[2][0]); t[2][1] = fma2(h23.x, b1, t[2][1]);
                t[2][2] = fma2(h23.x, b2, t[2][2]); t[2][3] = fma2(h23.x, b3, t[2][3]);
                t[3][0] = fma2(h23.y, b0, t[3][0]); t[3][1] = fma2(h23.y, b1, t[3][1]);
                t[3][2] = fma2(h23.y, b2, t[3][2]); t[3][3] = fma2(h23.y, b3, t[3][3]);
            }
            const ulonglong2 c01 = *reinterpret_cast<const ulonglong2*>(&Eas[j * 128 + eg]);
            const ulonglong2 c23 = *reinterpret_cast<const ulonglong2*>(&Eas[j * 128 + eg + 4]);
#pragma unroll
            for (int q = 0; q < 4; ++q) {
                acc[0][q] = fma2(c01.x, t[0][q], acc[0][q]);
                acc[1][q] = fma2(c01.y, t[1][q], acc[1][q]);
                acc[2][q] = fma2(c23.x, t[2][q], acc[2][q]);
                acc[3][q] = fma2(c23.y, t[3][q], acc[3][q]);
            }
            if (j < 16) {
                float4* d = reinterpret_cast<float4*>(Bs + ((j + 1) & 1) * 4096);
#pragma unroll
                for (int r = 0; r < 4; ++r) d[tid + r * 256] = breg[r];
            }
            __syncthreads();
        }

        // scatter: one v4 reduction per destination edge (16B-aligned quads)
#pragma unroll
        for (int a = 0; a < 4; ++a) {
            const int d0 = dst[e0 + eg + 2 * a];
            const int d1 = dst[e0 + eg + 2 * a + 1];
            const float2 v0 = unpack2(acc[a][0]);
            const float2 v1 = unpack2(acc[a][1]);
            const float2 v2 = unpack2(acc[a][2]);
            const float2 v3 = unpack2(acc[a][3]);
            red_add_v4(agg + (size_t)d0 * 64 + og, v0.x, v1.x, v2.x, v3.x);
            red_add_v4(agg + (size_t)d1 * 64 + og, v0.y, v1.y, v2.y, v3.y);
        }
    } else {
        // ------------- root path -------------
        float* Hs = sm;           // [64][64]  Hs[i*64+node]
        float* Bs = sm + 4096;    // [64][64]
        const int n0 = (blockIdx.x - E_TILES) * 64;
        {
            const int e = tid & 63;
            const float4* hp = reinterpret_cast<const float4*>(h + (size_t)(n0 + e) * 64);
#pragma unroll
            for (int r = 0; r < 4; ++r) {
                const int i4 = (tid >> 6) + r * 4;
                float4 v = hp[i4];
                if (RELU) { v.x = fmaxf(v.x, 0.f); v.y = fmaxf(v.y, 0.f); v.z = fmaxf(v.z, 0.f); v.w = fmaxf(v.w, 0.f); }
                Hs[(i4 * 4 + 0) * 64 + e] = v.x; Hs[(i4 * 4 + 1) * 64 + e] = v.y;
                Hs[(i4 * 4 + 2) * 64 + e] = v.z; Hs[(i4 * 4 + 3) * 64 + e] = v.w;
            }
        }
        for (int idx = tid; idx < 1024; idx += 256)
            reinterpret_cast<float4*>(Bs)[idx] = reinterpret_cast<const float4*>(root)[idx];
        __syncthreads();

        const int ty4 = (tid >> 4) * 4;
        const int tx4 = (tid & 15) * 4;
        float acc[4][4];
        const float4 bb = *reinterpret_cast<const float4*>(bias + tx4);
#pragma unroll
        for (int a = 0; a < 4; ++a) { acc[a][0] = bb.x; acc[a][1] = bb.y; acc[a][2] = bb.z; acc[a][3] = bb.w; }
#pragma unroll
        for (int i = 0; i < 64; ++i) {
            float hv[4], bv[4];
            *reinterpret_cast<float4*>(hv) = *reinterpret_cast<const float4*>(&Hs[i * 64 + ty4]);
            *reinterpret_cast<float4*>(bv) = *reinterpret_cast<const float4*>(&Bs[i * 64 + tx4]);
#pragma unroll
            for (int a = 0; a < 4; ++a)
#pragma unroll
                for (int q = 0; q < 4; ++q) acc[a][q] = fmaf(hv[a], bv[q], acc[a][q]);
        }
#pragma unroll
        for (int a = 0; a < 4; ++a)
            red_add_v4(agg + (size_t)(n0 + ty4 + a) * 64 + tx4,
                       acc[a][0], acc[a][1], acc[a][2], acc[a][3]);
    }
}

// ---------------------------------------------------------------------------
// Readout stage A: per-atom attention scores. Grid = 2500, 32 atoms/block.
// ---------------------------------------------------------------------------
__global__ __launch_bounds__(256) void score_kernel(const float* __restrict__ attw)
{
    const int tid = threadIdx.x;
    const int q = tid & 7;
    const int atom = blockIdx.x * 32 + (tid >> 3);
    GDS();
    const float4 aw0 = *reinterpret_cast<const float4*>(attw + q * 8);
    const float4 aw1 = *reinterpret_cast<const float4*>(attw + q * 8 + 4);
    const float* hr = g_h2 + (size_t)atom * 64 + q * 8;
    const float4 u0 = *reinterpret_cast<const float4*>(hr);
    const float4 u1 = *reinterpret_cast<const float4*>(hr + 4);
    float v = fmaxf(u0.x, 0.f) * aw0.x + fmaxf(u0.y, 0.f) * aw0.y +
              fmaxf(u0.z, 0.f) * aw0.z + fmaxf(u0.w, 0.f) * aw0.w +
              fmaxf(u1.x, 0.f) * aw1.x + fmaxf(u1.y, 0.f) * aw1.y +
              fmaxf(u1.z, 0.f) * aw1.z + fmaxf(u1.w, 0.f) * aw1.w;
    v += __shfl_xor_sync(0xffffffffu, v, 4);
    v += __shfl_xor_sync(0xffffffffu, v, 2);
    v += __shfl_xor_sync(0xffffffffu, v, 1);
    if (q == 0) g_sc[atom] = v;
}

// ---------------------------------------------------------------------------
// Readout stage B: per-graph softmax over 2500 scores + zero amino.
// ---------------------------------------------------------------------------
__global__ __launch_bounds__(256) void softmax_kernel()
{
    __shared__ float red[256];
    const int b = blockIdx.x;
    const int tid = threadIdx.x;
    float* sc = g_sc + (size_t)b * NG;
    GDS();

    for (int i = tid; i < NA * HDIM; i += 256)
        g_amino[(size_t)b * NA * HDIM + i] = 0.f;

    float m = -1e30f;
    for (int a = tid; a < NG; a += 256) m = fmaxf(m, sc[a]);
    red[tid] = m; __syncthreads();
    for (int s = 128; s; s >>= 1) { if (tid < s) red[tid] = fmaxf(red[tid], red[tid + s]); __syncthreads(); }
    const float mx = red[0]; __syncthreads();

    float ssum = 0.f;
    for (int a = tid; a < NG; a += 256) ssum += expf(sc[a] - mx);
    red[tid] = ssum; __syncthreads();
    for (int s = 128; s; s >>= 1) { if (tid < s) red[tid] += red[tid + s]; __syncthreads(); }
    const float inv = 1.f / red[0];
    __syncthreads();
    for (int a = tid; a < NG; a += 256) sc[a] = expf(sc[a] - mx) * inv;
}

// ---------------------------------------------------------------------------
// Readout stage C: weighted residue accumulation. Grid = NB*50, 64 threads,
// 50 contiguous atoms per block; run-length by label, atomics at boundaries.
// ---------------------------------------------------------------------------
__global__ __launch_bounds__(64) void accum_kernel(const int* __restrict__ labels)
{
    const int b = blockIdx.x / 50;
    const int chunk = blockIdx.x % 50;
    const int d = threadIdx.x;
    const int a0 = chunk * 50;
    GDS();
    const float* h2b = g_h2 + (size_t)b * NG * 64;
    const float* sc = g_sc + (size_t)b * NG;
    const int* lb = labels + (size_t)b * NG;
    float* am = g_amino + (size_t)b * NA * HDIM;

    float acc = 0.f; int cur = -1;
    for (int a = a0; a < a0 + 50; ++a) {
        const int lab = lb[a];
        if (lab != cur) {
            if (cur >= 0) atomicAdd(&am[cur * HDIM + d], acc);
            cur = lab; acc = 0.f;
        }
        acc = fmaf(sc[a], fmaxf(h2b[(size_t)a * 64 + d], 0.f), acc);
    }
    if (cur >= 0) atomicAdd(&am[cur * HDIM + d], acc);
}

// ---------------------------------------------------------------------------
// ARMA root/init terms: 21 GEMMs [1600,159] x [159,128] (+bias), split-N,
// FFMA2 row-packed. Reads amino+aaf directly (xi row gr = amino[gr] ‖ aaf[gr]).
// ---------------------------------------------------------------------------
__global__ __launch_bounds__(256) void armaR_kernel(
    const float* __restrict__ aaf, const float* __restrict__ initw,
    const float* __restrict__ rootw, const float* __restrict__ abias,
    float* __restrict__ z0, float* __restrict__ Rout)
{
    extern __shared__ float smr[];
    float* Xt = smr;                 // [159][68]  Xt[i*68+r]
    float* Ws = smr + FIN * 68;      // [159][64]
    const int blk = blockIdx.x;
    const int c = blk / 50;
    const int rem = blk % 50;
    const int chunk = rem >> 1;
    const int half = rem & 1;
    const int row0 = chunk * 64;
    const int tid = threadIdx.x;

    const float* W;
    const float* bias = nullptr;
    float* out;
    if (c < 3) { W = initw + (size_t)c * FIN * HG; out = z0 + (size_t)c * NB * NA * HG; }
    else {
        const int u = c - 3;
        W = rootw + (size_t)u * FIN * HG;
        bias = abias + (size_t)u * HG;
        out = Rout + (size_t)u * NB * NA * HG;
    }
    {
        const float4* W4 = reinterpret_cast<const float4*>(W);
        float4* Ws4 = reinterpret_cast<float4*>(Ws);
        for (int idx4 = tid; idx4 < FIN * 16; idx4 += 256) {
            const int i = idx4 >> 4, o4 = idx4 & 15;
            Ws4[idx4] = W4[i * 32 + half * 16 + o4];
        }
    }
    GDS();
    {
        for (int idx = tid; idx < 64 * FIN; idx += 256) {
            const int r = idx / FIN, i = idx - r * FIN;
            const int gr = row0 + r;
            const float v = (i < 64) ? g_amino[(size_t)gr * 64 + i]
                                     : aaf[(size_t)gr * AF + (i - 64)];
            Xt[i * 68 + r] = v;
        }
    }
    __syncthreads();

    const int rowg = (tid >> 4) * 4;   // 16 groups of 4 rows (2 pairs)
    const int colg = (tid & 15) * 4;   // 16 groups of 4 cols (within half)
    ull acc[2][4];
    {
        float bv[4] = {0.f, 0.f, 0.f, 0.f};
        if (bias) *reinterpret_cast<float4*>(bv) = *reinterpret_cast<const float4*>(bias + half * 64 + colg);
#pragma unroll
        for (int p = 0; p < 2; ++p)
#pragma unroll
            for (int q = 0; q < 4; ++q) acc[p][q] = pack2(bv[q], bv[q]);
    }
#pragma unroll 4
    for (int i = 0; i < FIN; ++i) {
        const ulonglong2 hp = *reinterpret_cast<const ulonglong2*>(&Xt[i * 68 + rowg]);
        float bv[4];
        *reinterpret_cast<float4*>(bv) = *reinterpret_cast<const float4*>(&Ws[i * 64 + colg]);
        const ull b0 = pack2(bv[0], bv[0]), b1 = pack2(bv[1], bv[1]);
        const ull b2 = pack2(bv[2], bv[2]), b3 = pack2(bv[3], bv[3]);
        acc[0][0] = fma2(hp.x, b0, acc[0][0]); acc[0][1] = fma2(hp.x, b1, acc[0][1]);
        acc[0][2] = fma2(hp.x, b2, acc[0][2]); acc[0][3] = fma2(hp.x, b3, acc[0][3]);
        acc[1][0] = fma2(hp.y, b0, acc[1][0]); acc[1][1] = fma2(hp.y, b1, acc[1][1]);
        acc[1][2] = fma2(hp.y, b2, acc[1][2]); acc[1][3] = fma2(hp.y, b3, acc[1][3]);
    }
#pragma unroll
    for (int p = 0; p < 2; ++p) {
        const float2 u0 = unpack2(acc[p][0]), u1 = unpack2(acc[p][1]);
        const float2 u2 = unpack2(acc[p][2]), u3 = unpack2(acc[p][3]);
        float4 ra; ra.x = u0.x; ra.y = u1.x; ra.z = u2.x; ra.w = u3.x;
        float4 rb; rb.x = u0.y; rb.y = u1.y; rb.z = u2.y; rb.w = u3.y;
        *reinterpret_cast<float4*>(out + (size_t)(row0 + rowg + 2 * p) * HG + half * 64 + colg) = ra;
        *reinterpret_cast<float4*>(out + (size_t)(row0 + rowg + 2 * p + 1) * HG + half * 64 + colg) = rb;
    }
}

// ---------------------------------------------------------------------------
// ARMA recurrence, fused over T. Block per (k, b). 512 threads, FFMA2 GEMM.
// ---------------------------------------------------------------------------
__global__ __launch_bounds__(512) void arma_iter_kernel(
    const float* __restrict__ armaw, const float* __restrict__ z0,
    const float* __restrict__ R, float* __restrict__ outF)
{
    extern __shared__ float sma[];
    float* St  = sma;                    // [128][68]  St[g*68+a]
    float* Y   = sma + 128 * 68;         // [64][128]
    float* Wsm = sma + 128 * 68 + 8192;  // [128][128]
    const int k = blockIdx.x / NB;
    const int b = blockIdx.x % NB;
    const int tid = threadIdx.x;
    GDS();

    const float* Z0p = z0 + ((size_t)k * (NB * NA) + b * NA) * HG;
    const float* R0  = R  + ((size_t)k * (NB * NA) + b * NA) * HG;
    for (int idx = tid; idx < 128 * 64; idx += 512) {
        const int a = idx & 63, g = idx >> 6;
        float v = 0.f;
        if (a < NA) {
            const float zv = (a >= 2) ? Z0p[(a - 1) * HG + g] : 0.f;
            v = fmaxf(zv + R0[a * HG + g], 0.f);
        }
        St[g * 68 + a] = v;
    }

    const int a4 = (tid >> 5) * 4;
    const int g4 = (tid & 31) * 4;

    for (int t = 1; t < TLY; ++t) {
        __syncthreads();
        const float* W = armaw + (size_t)((t - 1) * KST + k) * (HG * HG);
        for (int idx = tid; idx < (HG * HG) / 4; idx += 512)
            reinterpret_cast<float4*>(Wsm)[idx] = reinterpret_cast<const float4*>(W)[idx];
        __syncthreads();

        ull acc[4][2];
#pragma unroll
        for (int a = 0; a < 4; ++a) { acc[a][0] = 0ull; acc[a][1] = 0ull; }
#pragma unroll 8
        for (int kk = 0; kk < HG; ++kk) {
            float sv[4];
            *reinterpret_cast<float4*>(sv) = *reinterpret_cast<const float4*>(&St[kk * 68 + a4]);
            const ulonglong2 wv = *reinterpret_cast<const ulonglong2*>(&Wsm[kk * 128 + g4]);
#pragma unroll
            for (int a = 0; a < 4; ++a) {
                const ull sd = pack2(sv[a], sv[a]);
                acc[a][0] = fma2(sd, wv.x, acc[a][0]);
                acc[a][1] = fma2(sd, wv.y, acc[a][1]);
            }
        }
#pragma unroll
        for (int a = 0; a < 4; ++a) {
            ulonglong2 o; o.x = acc[a][0]; o.y = acc[a][1];
            *reinterpret_cast<ulonglong2*>(&Y[(a4 + a) * 128 + g4]) = o;
        }
        __syncthreads();

        const float* Rt = R + ((size_t)(t * KST + k) * (NB * NA) + b * NA) * HG;
        for (int idx = tid; idx < 128 * 64; idx += 512) {
            const int a = idx & 63, g = idx >> 6;
            float v = 0.f;
            if (a < NA) {
                const float yv = (a >= 2) ? Y[(a - 1) * 128 + g] : 0.f;
                v = fmaxf(yv + Rt[a * HG + g], 0.f);
            }
            St[g * 68 + a] = v;
        }
    }
    __syncthreads();
    float* out = outF + ((size_t)k * NB + b) * (NA * HG);
    for (int idx = tid; idx < NA * HG; idx += 512) {
        const int a = idx >> 7, g = idx & 127;
        out[idx] = St[g * 68 + a];
    }
}

// ---------------------------------------------------------------------------
// Final: g = relu(mean_k outF), residue attention, weighted sum, MLP head.
// ---------------------------------------------------------------------------
__global__ __launch_bounds__(256) void final_kernel(
    const float* __restrict__ outF, const float* __restrict__ attw,
    const float* __restrict__ w1, const float* __restrict__ b1,
    const float* __restrict__ w2, const float* __restrict__ b2,
    const float* __restrict__ w3, const float* __restrict__ b3,
    const float* __restrict__ w4, const float* __restrict__ b4,
    float* __restrict__ outp)
{
    __shared__ float G[NA * HG];
    __shared__ float scw[NA];
    __shared__ float P[HG];
    __shared__ float L1s[64], L2s[32], L3s[16];
    __shared__ float stats[1];
    const int b = blockIdx.x;
    const int tid = threadIdx.x;
    const int wid = tid >> 5, lane = tid & 31;
    GDS();

    const float* f0 = outF + ((size_t)0 * NB + b) * (NA * HG);
    const float* f1 = outF + ((size_t)1 * NB + b) * (NA * HG);
    const float* f2 = outF + ((size_t)2 * NB + b) * (NA * HG);
    for (int idx = tid; idx < NA * HG; idx += 256)
        G[idx] = fmaxf((f0[idx] + f1[idx] + f2[idx]) * (1.f / 3.f), 0.f);
    __syncthreads();

    for (int a = wid; a < NA; a += 8) {
        float v = 0.f;
#pragma unroll
        for (int q = 0; q < 4; ++q) v = fmaf(G[a * HG + lane + q * 32], attw[lane + q * 32], v);
#pragma unroll
        for (int off = 16; off; off >>= 1) v += __shfl_xor_sync(0xffffffffu, v, off);
        if (!lane) scw[a] = v;
    }
    __syncthreads();
    if (tid == 0) {
        float m = -1e30f;
        for (int a = 0; a < NA; ++a) m = fmaxf(m, scw[a]);
        float s = 0.f;
        for (int a = 0; a < NA; ++a) { const float w = expf(scw[a] - m); scw[a] = w; s += w; }
        stats[0] = 1.f / s;
    }
    __syncthreads();
    const float inv = stats[0];
    if (tid < HG) {
        float acc = 0.f;
        for (int a = 0; a < NA; ++a) acc = fmaf(G[a * HG + tid], scw[a], acc);
        P[tid] = acc * inv;
    }
    __syncthreads();
    if (tid < 64) {
        float acc = b1[tid];
        for (int i = 0; i < 128; ++i) acc = fmaf(P[i], w1[i * 64 + tid], acc);
        L1s[tid] = fmaxf(acc, 0.f);
    }
    __syncthreads();
    if (tid < 32) {
        float acc = b2[tid];
        for (int i = 0; i < 64; ++i) acc = fmaf(L1s[i], w2[i * 32 + tid], acc);
        L2s[tid] = fmaxf(acc, 0.f);
    }
    __syncthreads();
    if (tid < 16) {
        float acc = b3[tid];
        for (int i = 0; i < 32; ++i) acc = fmaf(L2s[i], w3[i * 16 + tid], acc);
        L3s[tid] = fmaxf(acc, 0.f);
    }
    __syncthreads();
    if (tid == 0) {
        float acc = b4[0];
        for (int i = 0; i < 16; ++i) acc = fmaf(L3s[i], w4[i], acc);
        outp[b] = acc;
    }
}

// ---------------------------------------------------------------------------
// PDL launch helper: secondary may begin while predecessor drains; the kernel
// gates dependent reads via cudaGridDependencySynchronize().
// ---------------------------------------------------------------------------
template <typename F, typename... Args>
static inline void launch_pdl(F f, dim3 grid, dim3 block, size_t smem, Args... args)
{
    cudaLaunchConfig_t cfg = {};
    cfg.gridDim = grid;
    cfg.blockDim = block;
    cfg.dynamicSmemBytes = smem;
    cudaLaunchAttribute attr[1];
    attr[0].id = cudaLaunchAttributeProgrammaticStreamSerialization;
    attr[0].val.programmaticStreamSerializationAllowed = 1;
    cfg.attrs = attr;
    cfg.numAttrs = 1;
    cudaLaunchKernelEx(&cfg, f, args...);
}

// ---------------------------------------------------------------------------
extern "C" void kernel_launch(void* const* d_in, const int* in_sizes, int n_in,
                              void* d_out, int out_size)
{
    const float* x        = (const float*)d_in[0];
    const int*   eidx     = (const int*)d_in[1];
    const float* eattr    = (const float*)d_in[2];
    const int*   labels   = (const int*)d_in[3];
    const float* aaf      = (const float*)d_in[4];
    const float* w_e1     = (const float*)d_in[5];
    const float* b_e1     = (const float*)d_in[6];
    const float* root1    = (const float*)d_in[7];
    const float* bias1    = (const float*)d_in[8];
    const float* w_e2     = (const float*)d_in[9];
    const float* b_e2     = (const float*)d_in[10];
    const float* root2    = (const float*)d_in[11];
    const float* bias2    = (const float*)d_in[12];
    const float* attwAtom = (const float*)d_in[13];
    const float* initw    = (const float*)d_in[15];
    const float* armaw    = (const float*)d_in[16];
    const float* rootw    = (const float*)d_in[17];
    const float* abias    = (const float*)d_in[18];
    const float* attwAA   = (const float*)d_in[19];
    const float* w1 = (const float*)d_in[21];
    const float* b1 = (const float*)d_in[22];
    const float* w2 = (const float*)d_in[23];
    const float* b2 = (const float*)d_in[24];
    const float* w3 = (const float*)d_in[25];
    const float* b3 = (const float*)d_in[26];
    const float* w4 = (const float*)d_in[27];
    const float* b4 = (const float*)d_in[28];
    float* outp = (float*)d_out;

    float *h1p, *h2p, *z0p, *Rp, *outFp;
    cudaGetSymbolAddress((void**)&h1p, g_h1);
    cudaGetSymbolAddress((void**)&h2p, g_h2);
    cudaGetSymbolAddress((void**)&z0p, g_Z0);
    cudaGetSymbolAddress((void**)&Rp, g_R);
    cudaGetSymbolAddress((void**)&outFp, g_outF);

    const int smemC = (8192 + 8192 + 17 * 128) * sizeof(float);        // 74240
    const int smemR = (FIN * 68 + FIN * 64) * sizeof(float);           // 83952
    const int smemA = (128 * 68 + 8192 + HG * HG) * sizeof(float);     // 133120
    cudaFuncSetAttribute(conv_kernel<false>, cudaFuncAttributeMaxDynamicSharedMemorySize, smemC);
    cudaFuncSetAttribute(conv_kernel<true>,  cudaFuncAttributeMaxDynamicSharedMemorySize, smemC);
    cudaFuncSetAttribute(armaR_kernel, cudaFuncAttributeMaxDynamicSharedMemorySize, smemR);
    cudaFuncSetAttribute(arma_iter_kernel, cudaFuncAttributeMaxDynamicSharedMemorySize, smemA);

    const int* src = eidx;
    const int* dst = eidx + N_EDGES;

    // Zero accumulators (plain launch), then the PDL-chained pipeline.
    zero_kernel<<<1024, 256>>>(h1p, h2p);
    launch_pdl(conv_kernel<false>, dim3(E_TILES + R_TILES), dim3(256), smemC,
               x, src, dst, eattr, w_e1, b_e1, root1, bias1, h1p);
    launch_pdl(conv_kernel<true>, dim3(E_TILES + R_TILES), dim3(256), smemC,
               h1p, src, dst, eattr, w_e2, b_e2, root2, bias2, h2p);
    launch_pdl(score_kernel, dim3(NG * NB / 32), dim3(256), 0, attwAtom);
    launch_pdl(softmax_kernel, dim3(NB), dim3(256), 0);
    launch_pdl(accum_kernel, dim3(NB * 50), dim3(64), 0, labels);
    launch_pdl(armaR_kernel, dim3(21 * 50), dim3(256), (size_t)smemR,
               aaf, initw, rootw, abias, z0p, Rp);
    launch_pdl(arma_iter_kernel, dim3(NB * KST), dim3(512), (size_t)smemA,
               armaw, z0p, Rp, outFp);
    launch_pdl(final_kernel, dim3(NB), dim3(256), 0,
               outFp, attwAA, w1, b1, w2, b2, w3, b3, w4, b4, outp);
}